// round 3
// baseline (speedup 1.0000x reference)
#include <cuda_runtime.h>
#include <cuda_bf16.h>

#define BB 256
#define TT 4096
#define II 63
#define HH 50
#define FCC 64
#define OO 2

// Scratch (static __device__ arrays; no allocation in kernel_launch)
__device__ float g_xz[(size_t)BB * TT * HH];   // [B*T, H] input projection
__device__ float g_hT[BB * HH];                // final hidden states

// ---------------------------------------------------------------------------
// packed fp32x2 FMA (sm_100+): one instruction does two fp32 FMAs
// ---------------------------------------------------------------------------
__device__ __forceinline__ float2 ffma2(float2 a, float2 b, float2 c) {
    unsigned long long ua, ub, uc, ud;
    ua = *reinterpret_cast<unsigned long long*>(&a);
    ub = *reinterpret_cast<unsigned long long*>(&b);
    uc = *reinterpret_cast<unsigned long long*>(&c);
    asm("fma.rn.f32x2 %0, %1, %2, %3;" : "=l"(ud) : "l"(ua), "l"(ub), "l"(uc));
    return *reinterpret_cast<float2*>(&ud);
}

// ---------------------------------------------------------------------------
// Kernel 1: xz[b*t][j] = sum_i x[b*t][i] * W_ih[j][i] + b_ih[j]
// warp-per-row; lane l (<25) computes output pair (2l, 2l+1) with packed FMA.
// x row staged in smem DUPLICATED (x_i, x_i) so loads feed f32x2 directly.
// ---------------------------------------------------------------------------
__global__ void __launch_bounds__(256, 1)
xz_kernel(const float* __restrict__ x,
          const float* __restrict__ W_ih,
          const float* __restrict__ b_ih) {
    __shared__ float sx[8][128];  // per-warp duplicated x row (126 used)

    const int lane = threadIdx.x & 31;
    const int w    = threadIdx.x >> 5;
    const int gw   = blockIdx.x * 8 + w;       // global warp id
    const int nw   = gridDim.x * 8;            // total warps
    const int jp   = lane;                     // j-pair index, active < 25

    // Load weight pairs into registers: wr[i] = (W[2jp][i], W[2jp+1][i])
    float2 wr[II];
    float2 bias = make_float2(0.f, 0.f);
    if (jp < 25) {
#pragma unroll
        for (int i = 0; i < II; i++) {
            wr[i].x = __ldg(&W_ih[(2 * jp) * II + i]);
            wr[i].y = __ldg(&W_ih[(2 * jp + 1) * II + i]);
        }
        bias.x = __ldg(&b_ih[2 * jp]);
        bias.y = __ldg(&b_ih[2 * jp + 1]);
    }

    const long long ROWS = (long long)BB * TT;
    float2* sxd = reinterpret_cast<float2*>(sx[w]);

    for (long long row = gw; row < ROWS; row += nw) {
        const float* xr = x + row * II;
        // stage duplicated: sxd[i] = (x_i, x_i)
        float v0 = __ldg(&xr[lane]);             // lane 0..31, i=lane (<63 ok)
        sxd[lane] = make_float2(v0, v0);
        if (lane < II - 32) {
            float v1 = __ldg(&xr[32 + lane]);
            sxd[32 + lane] = make_float2(v1, v1);
        }
        __syncwarp();

        if (jp < 25) {
            float2 a0 = bias;
            float2 a1 = make_float2(0.f, 0.f);
            const float4* sxp4 = reinterpret_cast<const float4*>(sx[w]);
#pragma unroll
            for (int p = 0; p < 31; p++) {       // i = 2p, 2p+1 (0..61)
                float4 q = sxp4[p];
                a0 = ffma2(make_float2(q.x, q.y), wr[2 * p], a0);
                a1 = ffma2(make_float2(q.z, q.w), wr[2 * p + 1], a1);
            }
            {
                float2 x62 = sxd[62];            // i = 62
                a0 = ffma2(x62, wr[62], a0);
            }
            float2 r;
            r.x = a0.x + a1.x;
            r.y = a0.y + a1.y;
            *reinterpret_cast<float2*>(&g_xz[(size_t)row * HH + 2 * jp]) = r;
        }
        __syncwarp();
    }
}

// ---------------------------------------------------------------------------
// Kernel 2: the sequential scan. 128 CTAs x 128 threads; CTA handles 2 rows.
// thread (lrow, j) owns output j of its row; W_hh[j][:] in registers;
// h double-buffered in smem -> ONE __syncthreads per step;
// 8-deep register prefetch ring for xz (DRAM latency cover).
// ---------------------------------------------------------------------------
#define PF 8

__global__ void __launch_bounds__(128, 1)
scan_kernel(const float* __restrict__ W_hh,
            const float* __restrict__ b_hh) {
    __shared__ float hbuf[2][2][64];  // [buf][localrow][j], padded to 64 (16B align)

    const int tid    = threadIdx.x;
    const bool active = (tid < 2 * HH);
    const int lrow   = tid / HH;          // 0..1 (for active threads)
    const int j      = tid - lrow * HH;   // 0..49
    const int grow   = blockIdx.x * 2 + lrow;

    float w[HH];
    float bj = 0.f;
    if (active) {
#pragma unroll
        for (int k = 0; k < HH; k++) w[k] = __ldg(&W_hh[j * HH + k]);
        bj = __ldg(&b_hh[j]);
    }

    // h0 = 0
    ((float*)hbuf[0])[tid] = 0.f;

    const float* xzr = g_xz + (active ? ((size_t)grow * TT * HH + j) : 0);

    // prefetch ring
    float xzb[PF];
    if (active) {
#pragma unroll
        for (int p = 0; p < PF; p++) xzb[p] = __ldg(xzr + (size_t)p * HH);
    }

    float hlast = 0.f;
    int cb = 0;
    __syncthreads();

#pragma unroll 8
    for (int t = 0; t < TT; t++) {
        const int slot = t & (PF - 1);
        float xz_c = xzb[slot];
        if (active && (t + PF) < TT)
            xzb[slot] = __ldg(xzr + (size_t)(t + PF) * HH);

        if (active) {
            const float* hp = hbuf[cb][lrow];
            float a0 = xz_c + bj;
            float a1 = 0.f, a2 = 0.f, a3 = 0.f;
#pragma unroll
            for (int k4 = 0; k4 < 12; k4++) {
                float4 hv = *reinterpret_cast<const float4*>(hp + 4 * k4);
                a0 = fmaf(hv.x, w[4 * k4 + 0], a0);
                a1 = fmaf(hv.y, w[4 * k4 + 1], a1);
                a2 = fmaf(hv.z, w[4 * k4 + 2], a2);
                a3 = fmaf(hv.w, w[4 * k4 + 3], a3);
            }
            a0 = fmaf(hp[48], w[48], a0);
            a1 = fmaf(hp[49], w[49], a1);
            float pre = (a0 + a1) + (a2 + a3);
            hlast = tanhf(pre);
            hbuf[cb ^ 1][lrow][j] = hlast;
        }
        __syncthreads();
        cb ^= 1;
    }

    if (active) g_hT[grow * HH + j] = hlast;
}

// ---------------------------------------------------------------------------
// Kernel 3: MLP head + argmax.  thread per batch row.
// ---------------------------------------------------------------------------
__global__ void __launch_bounds__(64, 1)
head_kernel(const float* __restrict__ W1, const float* __restrict__ b1,
            const float* __restrict__ W2, const float* __restrict__ b2,
            float* __restrict__ out) {
    __shared__ float sW1[FCC * HH];
    __shared__ float sW2[OO * FCC];
    __shared__ float sb1[FCC];
    __shared__ float sb2[OO];

    const int tid = threadIdx.x;
    for (int i = tid; i < FCC * HH; i += blockDim.x) sW1[i] = W1[i];
    for (int i = tid; i < OO * FCC; i += blockDim.x) sW2[i] = W2[i];
    if (tid < FCC) sb1[tid] = b1[tid];
    if (tid < OO)  sb2[tid] = b2[tid];
    __syncthreads();

    const int row = blockIdx.x * blockDim.x + tid;
    if (row >= BB) return;

    float h[HH];
#pragma unroll
    for (int k = 0; k < HH; k++) h[k] = g_hT[row * HH + k];

    float l0 = sb2[0], l1 = sb2[1];
#pragma unroll 4
    for (int f = 0; f < FCC; f++) {
        float d = sb1[f];
#pragma unroll
        for (int k = 0; k < HH; k++) d = fmaf(h[k], sW1[f * HH + k], d);
        d = fmaxf(d, 0.f);
        l0 = fmaf(d, sW2[f], l0);
        l1 = fmaf(d, sW2[FCC + f], l1);
    }
    // softmax is monotone; argmax of logits. jnp.argmax picks FIRST max -> use strict >
    out[row] = (l1 > l0) ? 1.0f : 0.0f;
}

// ---------------------------------------------------------------------------
extern "C" void kernel_launch(void* const* d_in, const int* in_sizes, int n_in,
                              void* d_out, int out_size) {
    const float* x    = (const float*)d_in[0];
    const float* W_ih = (const float*)d_in[1];
    const float* b_ih = (const float*)d_in[2];
    const float* W_hh = (const float*)d_in[3];
    const float* b_hh = (const float*)d_in[4];
    const float* W1   = (const float*)d_in[5];
    const float* b1   = (const float*)d_in[6];
    const float* W2   = (const float*)d_in[7];
    const float* b2   = (const float*)d_in[8];
    float* out = (float*)d_out;

    // 148 CTAs: exactly one resident CTA per SM (reg-limited), grid-stride rows
    xz_kernel<<<148, 256>>>(x, W_ih, b_ih);
    // 128 CTAs x 128 thr: 1 CTA/SM, 1 warp/SMSP -> full FFMA issue rate per warp
    scan_kernel<<<128, 128>>>(W_hh, b_hh);
    head_kernel<<<4, 64>>>(W1, b1, W2, b2, out);
}